// round 11
// baseline (speedup 1.0000x reference)
#include <cuda_runtime.h>
#include <math.h>

#define NP 512
#define NB 512
#define NAT 32
#define NBT 40
#define NC 3
#define NTAB 40
#define NG 36
#define NA (NB*NAT)
#define TPB 256

// Full 4x4 Catmull-Rom patches: for each (tab, i, j) floor cell, the 16 values
// rows wrap(i-1..i+2) x cols wrap(j-1..j+2), as 4 float4 = one 64B-aligned chunk.
__device__ float4 g_patch[NTAB * NG * NG * 4];

__global__ void repack_tables_kernel(const float* __restrict__ tables) {
    const int idx = blockIdx.x * blockDim.x + threadIdx.x;
    if (idx >= NTAB * NG * NG) return;
    const int j   = idx % NG;
    const int i   = (idx / NG) % NG;
    const int tab = idx / (NG * NG);
    const float* t = tables + tab * NG * NG;
    int jj[4], ii[4];
    #pragma unroll
    for (int d = 0; d < 4; d++) {
        int a = i - 1 + d; if (a < 0) a += NG; if (a >= NG) a -= NG;
        int c = j - 1 + d; if (c < 0) c += NG; if (c >= NG) c -= NG;
        ii[d] = a; jj[d] = c;
    }
    #pragma unroll
    for (int d = 0; d < 4; d++) {
        const float* row = t + ii[d] * NG;
        g_patch[idx * 4 + d] = make_float4(row[jj[0]], row[jj[1]], row[jj[2]], row[jj[3]]);
    }
}

__device__ __forceinline__ int wrapG(int v) {
    int m = v % NG;
    return (m < 0) ? m + NG : m;
}

__device__ __forceinline__ void cr_weights(float f, float w[4]) {
    float f2 = f * f;
    float f3 = f2 * f;
    w[0] = 0.5f * (-f3 + 2.0f * f2 - f);
    w[1] = 0.5f * (3.0f * f3 - 5.0f * f2 + 2.0f);
    w[2] = 0.5f * (-3.0f * f3 + 4.0f * f2 + f);
    w[3] = 0.5f * (f3 - f2);
}

__device__ __forceinline__ float dihedral(
    const float x[4], const float y[4], const float z[4])
{
    float b1x = x[1]-x[0], b1y = y[1]-y[0], b1z = z[1]-z[0];
    float b2x = x[2]-x[1], b2y = y[2]-y[1], b2z = z[2]-z[1];
    float b3x = x[3]-x[2], b3y = y[3]-y[2], b3z = z[3]-z[2];
    float n1x = b1y*b2z - b1z*b2y;
    float n1y = b1z*b2x - b1x*b2z;
    float n1z = b1x*b2y - b1y*b2x;
    float n2x = b2y*b3z - b2z*b3y;
    float n2y = b2z*b3x - b2x*b3z;
    float n2z = b2x*b3y - b2y*b3x;
    float b2n = sqrtf(b2x*b2x + b2y*b2y + b2z*b2z) + 1e-12f;
    float inv = 1.0f / b2n;
    float ux = b2x*inv, uy = b2y*inv, uz = b2z*inv;
    float m1x = n1y*uz - n1z*uy;
    float m1y = n1z*ux - n1x*uz;
    float m1z = n1x*uy - n1y*ux;
    float xx = n1x*n2x + n1y*n2y + n1z*n2z;
    float yy = m1x*n2x + m1y*n2y + m1z*n2z;
    return atan2f(yy, xx);
}

// Branchless xyz load: 1 unconditional LDG.128 + 1 LDG.64 predicated on r>=2.
__device__ __forceinline__ void load_xyz(
    const float4* __restrict__ cp4, const float2* __restrict__ cp2,
    int gidx, float& x, float& y, float& z)
{
    const int base = gidx * 3;
    const int r = base & 3;
    const float4 V = __ldg(cp4 + (base >> 2));
    float2 E = make_float2(0.0f, 0.0f);
    if (r >= 2) E = __ldg(cp2 + ((base + 2) >> 1));
    x = (r == 0) ? V.x : ((r == 1) ? V.y : ((r == 2) ? V.z : V.w));
    y = (r == 0) ? V.y : ((r == 1) ? V.z : ((r == 2) ? V.w : E.x));
    z = (r == 0) ? V.z : ((r == 1) ? V.w : ((r == 2) ? E.x : E.y));
}

__global__ __launch_bounds__(TPB, 4) void rama_kernel(
    const float* __restrict__ coords,        // (P, NA, 3)
    const int*   __restrict__ offsets,       // (P, B)
    const int*   __restrict__ block_type,    // (P, B)
    const int*   __restrict__ inter,         // (P, B, NC, 2)
    const int*   __restrict__ down,          // (NBT, NC, NAT)
    const int*   __restrict__ bt_rama_table, // (NBT, 2)
    const int*   __restrict__ bt_upper,      // (NBT)
    const int*   __restrict__ bt_is_pro,     // (NBT)
    const int*   __restrict__ tor_atoms,     // (NBT, 8, 3)
    const float* __restrict__ tparams,       // (NTAB, 2, 2)
    float*       __restrict__ out)           // (P,)
{
    __shared__ int   s_offs[NB];
    __shared__ int   s_bt[NB];
    __shared__ int4  s_torpack[NBT];
    __shared__ alignas(16) int   s_down[NBT * NC * NAT];
    __shared__ int   s_tabsel[NBT * 2];
    __shared__ int   s_upper[NBT];
    __shared__ int   s_ispro[NBT];
    __shared__ float s_tp[NTAB * 4];
    __shared__ float s_warp[TPB / 32];

    const int p   = blockIdx.x;
    const int tid = threadIdx.x;

    // ---- stage pose rows (each thread: 2 coalesced entries) ----
    s_offs[tid]       = offsets[p * NB + tid];
    s_offs[tid + TPB] = offsets[p * NB + tid + TPB];
    s_bt[tid]         = block_type[p * NB + tid];
    s_bt[tid + TPB]   = block_type[p * NB + tid + TPB];
    {
        const int4* g4 = (const int4*)down;   // 960 int4
        int4* s4 = (int4*)s_down;
        #pragma unroll
        for (int i = tid; i < 960; i += TPB) s4[i] = g4[i];
    }
    if (tid < NBT) {
        const int* tr = tor_atoms + tid * 24;   // 8 slots x 3
        unsigned int w[4];
        #pragma unroll
        for (int h = 0; h < 4; h++) {
            unsigned int lo, hi;
            {
                const int s = 2 * h;
                const int ai = tr[s*3+0], ci = tr[s*3+1], nb = tr[s*3+2];
                lo = (unsigned int)(ai + 1) | ((unsigned int)(ci + 1) << 6)
                   | ((unsigned int)nb << 8);
            }
            {
                const int s = 2 * h + 1;
                const int ai = tr[s*3+0], ci = tr[s*3+1], nb = tr[s*3+2];
                hi = (unsigned int)(ai + 1) | ((unsigned int)(ci + 1) << 6)
                   | ((unsigned int)nb << 8);
            }
            w[h] = lo | (hi << 16);
        }
        s_torpack[tid] = make_int4((int)w[0], (int)w[1], (int)w[2], (int)w[3]);
    }
    if (tid < NBT * 2) s_tabsel[tid] = bt_rama_table[tid];
    if (tid < NBT)     { s_upper[tid] = bt_upper[tid]; s_ispro[tid] = bt_is_pro[tid]; }
    if (tid < NTAB*4)  s_tp[tid] = tparams[tid];

    // ---- per-thread inter rows for both items (issued before sync) ----
    int iv[2][6];
    #pragma unroll
    for (int k = 0; k < 2; k++) {
        const int pb = p * NB + tid + k * TPB;
        const int2* ip2 = (const int2*)(inter + (size_t)pb * 6);
        const int2 a = __ldg(ip2 + 0), bb = __ldg(ip2 + 1), c = __ldg(ip2 + 2);
        iv[k][0] = a.x;  iv[k][1] = a.y;
        iv[k][2] = bb.x; iv[k][3] = bb.y;
        iv[k][4] = c.x;  iv[k][5] = c.y;
    }

    __syncthreads();

    // ---- compute gather indices for both items ----
    int  gidx[2][8];
    bool ok[2];
    int  btk[2];
    #pragma unroll
    for (int k = 0; k < 2; k++) {
        const int b    = tid + k * TPB;
        const int bt   = s_bt[b];
        const int offb = s_offs[b];
        btk[k] = bt;
        const int4 tp4 = s_torpack[bt];
        bool okk = true;
        #pragma unroll
        for (int t = 0; t < 8; t++) {
            const unsigned int word = (unsigned int)((t >> 1) == 0 ? tp4.x :
                                      (t >> 1) == 1 ? tp4.y :
                                      (t >> 1) == 2 ? tp4.z : tp4.w);
            const unsigned int field = (t & 1) ? (word >> 16) : (word & 0xffffu);
            const int ai     = (int)(field & 63u) - 1;
            const int ci     = (int)((field >> 6) & 3u) - 1;
            const int nbonds = (int)((field >> 8) & 31u);
            int g;
            bool aok;
            if (ai >= 0) {
                g = offb + ai;
                aok = true;
            } else {
                const int sc = max(ci, 0);
                const int ob = (sc == 0) ? iv[k][0] : ((sc == 1) ? iv[k][2] : iv[k][4]);
                const int oc = (sc == 0) ? iv[k][1] : ((sc == 1) ? iv[k][3] : iv[k][5]);
                aok = (ci >= 0) && (ob >= 0);
                const int obc = min(max(ob, 0), NB - 1);
                const int occ = min(max(oc, 0), NC - 1);
                const int obt = s_bt[obc];
                const int da  = s_down[(obt * NC + occ) * NAT + nbonds];
                g = s_offs[obc] + da;
            }
            okk = okk && aok;
            gidx[k][t] = min(max(g, 0), NA - 1);
        }
        ok[k] = okk;
    }

    // ---- issue ALL coord loads (both items) for max MLP ----
    float ax[2][8], ay[2][8], az[2][8];
    const float4* cp4 = (const float4*)(coords + (size_t)p * NA * 3);
    const float2* cp2 = (const float2*)(coords + (size_t)p * NA * 3);
    #pragma unroll
    for (int k = 0; k < 2; k++) {
        #pragma unroll
        for (int t = 0; t < 8; t++) {
            const bool dup = (t >= 4 && t <= 6) && (gidx[k][t] == gidx[k][t-3]);
            if (dup) {
                ax[k][t] = ax[k][t-3]; ay[k][t] = ay[k][t-3]; az[k][t] = az[k][t-3];
            } else {
                load_xyz(cp4, cp2, gidx[k][t], ax[k][t], ay[k][t], az[k][t]);
            }
        }
    }

    // ---- dihedrals + patch interpolation per item ----
    float v = 0.0f;
    #pragma unroll
    for (int k = 0; k < 2; k++) {
        const float phi = dihedral(&ax[k][0], &ay[k][0], &az[k][0]);
        const float psi = dihedral(&ax[k][4], &ay[k][4], &az[k][4]);

        const int bt    = btk[k];
        const int uc    = min(max(s_upper[bt], 0), NC - 1);
        const int nbblk = (uc == 0) ? iv[k][0] : ((uc == 1) ? iv[k][2] : iv[k][4]);
        const bool nb_ok = (nbblk >= 0);
        const int nbt = s_bt[min(max(nbblk, 0), NB - 1)];
        const int tab = s_tabsel[bt * 2 + s_ispro[nbt]];

        const float start0 = s_tp[tab * 4 + 0];
        const float start1 = s_tp[tab * 4 + 1];
        const float step0  = s_tp[tab * 4 + 2];
        const float step1  = s_tp[tab * 4 + 3];

        const float u0 = (phi - start0) / step0;
        const float u1 = (psi - start1) / step1;
        const float i0f = floorf(u0);
        const float j0f = floorf(u1);
        const float f0 = u0 - i0f;
        const float f1 = u1 - j0f;
        const int i0 = (int)i0f;
        const int j0 = (int)j0f;

        float wp[4], wq[4];
        cr_weights(f0, wp);
        cr_weights(f1, wq);

        // one 64B-aligned patch: 4 consecutive float4 loads (same cache line pair)
        const int iw = wrapG(i0);
        const int jw = wrapG(j0);
        const int pbase = ((tab * NG + iw) * NG + jw) * 4;

        float4 tv[4];
        #pragma unroll
        for (int i = 0; i < 4; i++) tv[i] = __ldg(&g_patch[pbase + i]);

        float e = 0.0f;
        #pragma unroll
        for (int i = 0; i < 4; i++) {
            float acc;
            acc = wq[0] * tv[i].x;
            acc = fmaf(wq[1], tv[i].y, acc);
            acc = fmaf(wq[2], tv[i].z, acc);
            acc = fmaf(wq[3], tv[i].w, acc);
            e = fmaf(wp[i], acc, e);
        }

        v += (ok[k] && nb_ok) ? e : 0.0f;
    }

    // ---- block reduction: 8 warps ----
    const int lane = tid & 31;
    const int wid  = tid >> 5;
    #pragma unroll
    for (int o = 16; o > 0; o >>= 1)
        v += __shfl_down_sync(0xffffffffu, v, o);
    if (lane == 0) s_warp[wid] = v;
    __syncthreads();
    if (wid == 0) {
        float x = (lane < (TPB / 32)) ? s_warp[lane] : 0.0f;
        #pragma unroll
        for (int o = 4; o > 0; o >>= 1)
            x += __shfl_down_sync(0xffffffffu, x, o);
        if (lane == 0) out[p] = x;
    }
}

extern "C" void kernel_launch(void* const* d_in, const int* in_sizes, int n_in,
                              void* d_out, int out_size) {
    const float* coords        = (const float*)d_in[0];
    const int*   offsets       = (const int*)d_in[1];
    const int*   block_type    = (const int*)d_in[2];
    const int*   inter         = (const int*)d_in[3];
    const int*   down          = (const int*)d_in[4];
    const int*   bt_rama_table = (const int*)d_in[5];
    const int*   bt_upper      = (const int*)d_in[6];
    const int*   bt_is_pro     = (const int*)d_in[7];
    const int*   tor_atoms     = (const int*)d_in[8];
    const float* tables        = (const float*)d_in[9];
    const float* tparams       = (const float*)d_in[10];
    float* out = (float*)d_out;

    const int ncells = NTAB * NG * NG;
    repack_tables_kernel<<<(ncells + 255) / 256, 256>>>(tables);
    rama_kernel<<<NP, TPB>>>(coords, offsets, block_type, inter, down,
                             bt_rama_table, bt_upper, bt_is_pro, tor_atoms,
                             tparams, out);
}

// round 12
// speedup vs baseline: 1.0013x; 1.0013x over previous
#include <cuda_runtime.h>
#include <math.h>

#define NP 512
#define NB 512
#define NAT 32
#define NBT 40
#define NC 3
#define NTAB 40
#define NG 36
#define NA (NB*NAT)
#define TPB 256

// Repacked tables: for each (tab,row,c0), the 4 wrapped column taps as one float4.
__device__ float4 g_tbl4[NTAB * NG * NG];
// Per-item resolved gather indices (8 x u16) and meta (tab | ok<<8 | nb_ok<<9).
__device__ int4 g_pk[NP * NB];
__device__ int  g_meta[NP * NB];

__global__ void repack_tables_kernel(const float* __restrict__ tables) {
    const int idx = blockIdx.x * blockDim.x + threadIdx.x;
    if (idx >= NTAB * NG * NG) return;
    const int c0 = idx % NG;
    const float* row = tables + (idx / NG) * NG;
    int c1 = c0 + 1; if (c1 >= NG) c1 -= NG;
    int c2 = c0 + 2; if (c2 >= NG) c2 -= NG;
    int c3 = c0 + 3; if (c3 >= NG) c3 -= NG;
    g_tbl4[idx] = make_float4(row[c0], row[c1], row[c2], row[c3]);
}

__device__ __forceinline__ int wrapG(int v) {
    int m = v % NG;
    return (m < 0) ? m + NG : m;
}

__device__ __forceinline__ void cr_weights(float f, float w[4]) {
    float f2 = f * f;
    float f3 = f2 * f;
    w[0] = 0.5f * (-f3 + 2.0f * f2 - f);
    w[1] = 0.5f * (3.0f * f3 - 5.0f * f2 + 2.0f);
    w[2] = 0.5f * (-3.0f * f3 + 4.0f * f2 + f);
    w[3] = 0.5f * (f3 - f2);
}

__device__ __forceinline__ float dihedral(
    const float x[4], const float y[4], const float z[4])
{
    float b1x = x[1]-x[0], b1y = y[1]-y[0], b1z = z[1]-z[0];
    float b2x = x[2]-x[1], b2y = y[2]-y[1], b2z = z[2]-z[1];
    float b3x = x[3]-x[2], b3y = y[3]-y[2], b3z = z[3]-z[2];
    float n1x = b1y*b2z - b1z*b2y;
    float n1y = b1z*b2x - b1x*b2z;
    float n1z = b1x*b2y - b1y*b2x;
    float n2x = b2y*b3z - b2z*b3y;
    float n2y = b2z*b3x - b2x*b3z;
    float n2z = b2x*b3y - b2y*b3x;
    float b2n = sqrtf(b2x*b2x + b2y*b2y + b2z*b2z) + 1e-12f;
    float inv = 1.0f / b2n;
    float ux = b2x*inv, uy = b2y*inv, uz = b2z*inv;
    float m1x = n1y*uz - n1z*uy;
    float m1y = n1z*ux - n1x*uz;
    float m1z = n1x*uy - n1y*ux;
    float xx = n1x*n2x + n1y*n2y + n1z*n2z;
    float yy = m1x*n2x + m1y*n2y + m1z*n2z;
    return atan2f(yy, xx);
}

// Branchless xyz load: 1 unconditional LDG.128 + 1 LDG.64 predicated on r>=2.
__device__ __forceinline__ void load_xyz(
    const float4* __restrict__ cp4, const float2* __restrict__ cp2,
    int gidx, float& x, float& y, float& z)
{
    const int base = gidx * 3;
    const int r = base & 3;
    const float4 V = __ldg(cp4 + (base >> 2));
    float2 E = make_float2(0.0f, 0.0f);
    if (r >= 2) E = __ldg(cp2 + ((base + 2) >> 1));
    x = (r == 0) ? V.x : ((r == 1) ? V.y : ((r == 2) ? V.z : V.w));
    y = (r == 0) ? V.y : ((r == 1) ? V.z : ((r == 2) ? V.w : E.x));
    z = (r == 0) ? V.z : ((r == 1) ? V.w : ((r == 2) ? E.x : E.y));
}

// ============ Kernel B: resolve all gather indices + table selection ============
__global__ __launch_bounds__(TPB, 4) void prep_kernel(
    const int*   __restrict__ offsets,       // (P, B)
    const int*   __restrict__ block_type,    // (P, B)
    const int*   __restrict__ inter,         // (P, B, NC, 2)
    const int*   __restrict__ down,          // (NBT, NC, NAT)
    const int*   __restrict__ bt_rama_table, // (NBT, 2)
    const int*   __restrict__ bt_upper,      // (NBT)
    const int*   __restrict__ bt_is_pro,     // (NBT)
    const int*   __restrict__ tor_atoms)     // (NBT, 8, 3)
{
    __shared__ int   s_offs[NB];
    __shared__ int   s_bt[NB];
    __shared__ int4  s_torpack[NBT];
    __shared__ alignas(16) int   s_down[NBT * NC * NAT];
    __shared__ int   s_tabsel[NBT * 2];
    __shared__ int   s_upper[NBT];
    __shared__ int   s_ispro[NBT];

    const int p   = blockIdx.x;
    const int tid = threadIdx.x;

    s_offs[tid]       = offsets[p * NB + tid];
    s_offs[tid + TPB] = offsets[p * NB + tid + TPB];
    s_bt[tid]         = block_type[p * NB + tid];
    s_bt[tid + TPB]   = block_type[p * NB + tid + TPB];
    {
        const int4* g4 = (const int4*)down;   // 960 int4
        int4* s4 = (int4*)s_down;
        #pragma unroll
        for (int i = tid; i < 960; i += TPB) s4[i] = g4[i];
    }
    if (tid < NBT) {
        const int* tr = tor_atoms + tid * 24;   // 8 slots x 3
        unsigned int w[4];
        #pragma unroll
        for (int h = 0; h < 4; h++) {
            unsigned int lo, hi;
            {
                const int s = 2 * h;
                const int ai = tr[s*3+0], ci = tr[s*3+1], nb = tr[s*3+2];
                lo = (unsigned int)(ai + 1) | ((unsigned int)(ci + 1) << 6)
                   | ((unsigned int)nb << 8);
            }
            {
                const int s = 2 * h + 1;
                const int ai = tr[s*3+0], ci = tr[s*3+1], nb = tr[s*3+2];
                hi = (unsigned int)(ai + 1) | ((unsigned int)(ci + 1) << 6)
                   | ((unsigned int)nb << 8);
            }
            w[h] = lo | (hi << 16);
        }
        s_torpack[tid] = make_int4((int)w[0], (int)w[1], (int)w[2], (int)w[3]);
    }
    if (tid < NBT * 2) s_tabsel[tid] = bt_rama_table[tid];
    if (tid < NBT)     { s_upper[tid] = bt_upper[tid]; s_ispro[tid] = bt_is_pro[tid]; }

    int iv[2][6];
    #pragma unroll
    for (int k = 0; k < 2; k++) {
        const int pb = p * NB + tid + k * TPB;
        const int2* ip2 = (const int2*)(inter + (size_t)pb * 6);
        const int2 a = __ldg(ip2 + 0), bb = __ldg(ip2 + 1), c = __ldg(ip2 + 2);
        iv[k][0] = a.x;  iv[k][1] = a.y;
        iv[k][2] = bb.x; iv[k][3] = bb.y;
        iv[k][4] = c.x;  iv[k][5] = c.y;
    }

    __syncthreads();

    #pragma unroll
    for (int k = 0; k < 2; k++) {
        const int b    = tid + k * TPB;
        const int pb   = p * NB + b;
        const int bt   = s_bt[b];
        const int offb = s_offs[b];
        const int4 tp4 = s_torpack[bt];
        bool okk = true;
        int g[8];
        #pragma unroll
        for (int t = 0; t < 8; t++) {
            const unsigned int word = (unsigned int)((t >> 1) == 0 ? tp4.x :
                                      (t >> 1) == 1 ? tp4.y :
                                      (t >> 1) == 2 ? tp4.z : tp4.w);
            const unsigned int field = (t & 1) ? (word >> 16) : (word & 0xffffu);
            const int ai     = (int)(field & 63u) - 1;
            const int ci     = (int)((field >> 6) & 3u) - 1;
            const int nbonds = (int)((field >> 8) & 31u);
            int gg;
            bool aok;
            if (ai >= 0) {
                gg = offb + ai;
                aok = true;
            } else {
                const int sc = max(ci, 0);
                const int ob = (sc == 0) ? iv[k][0] : ((sc == 1) ? iv[k][2] : iv[k][4]);
                const int oc = (sc == 0) ? iv[k][1] : ((sc == 1) ? iv[k][3] : iv[k][5]);
                aok = (ci >= 0) && (ob >= 0);
                const int obc = min(max(ob, 0), NB - 1);
                const int occ = min(max(oc, 0), NC - 1);
                const int obt = s_bt[obc];
                const int da  = s_down[(obt * NC + occ) * NAT + nbonds];
                gg = s_offs[obc] + da;
            }
            okk = okk && aok;
            g[t] = min(max(gg, 0), NA - 1);
        }

        const int uc    = min(max(s_upper[bt], 0), NC - 1);
        const int nbblk = (uc == 0) ? iv[k][0] : ((uc == 1) ? iv[k][2] : iv[k][4]);
        const bool nb_ok = (nbblk >= 0);
        const int nbt = s_bt[min(max(nbblk, 0), NB - 1)];
        const int tab = s_tabsel[bt * 2 + s_ispro[nbt]];

        int4 pk;
        pk.x = g[0] | (g[1] << 16);
        pk.y = g[2] | (g[3] << 16);
        pk.z = g[4] | (g[5] << 16);
        pk.w = g[6] | (g[7] << 16);
        g_pk[pb]   = pk;
        g_meta[pb] = tab | (okk ? 0x100 : 0) | (nb_ok ? 0x200 : 0);
    }
}

// ============ Kernel C: gather coords, dihedrals, table energy, reduce ============
__global__ __launch_bounds__(TPB, 4) void score_kernel(
    const float* __restrict__ coords,        // (P, NA, 3)
    const float* __restrict__ tparams,       // (NTAB, 2, 2)
    float*       __restrict__ out)           // (P,)
{
    __shared__ float s_warp[TPB / 32];

    const int p   = blockIdx.x;
    const int tid = threadIdx.x;

    const float4* cp4 = (const float4*)(coords + (size_t)p * NA * 3);
    const float2* cp2 = (const float2*)(coords + (size_t)p * NA * 3);

    // load packed indices + meta for both items up-front
    int4 pk[2];
    int  meta[2];
    #pragma unroll
    for (int k = 0; k < 2; k++) {
        const int pb = p * NB + tid + k * TPB;
        pk[k]   = __ldg(&g_pk[pb]);
        meta[k] = __ldg(&g_meta[pb]);
    }

    // decode indices and issue all coord loads
    int gidx[2][8];
    float ax[2][8], ay[2][8], az[2][8];
    #pragma unroll
    for (int k = 0; k < 2; k++) {
        gidx[k][0] = pk[k].x & 0xffff;  gidx[k][1] = ((unsigned)pk[k].x) >> 16;
        gidx[k][2] = pk[k].y & 0xffff;  gidx[k][3] = ((unsigned)pk[k].y) >> 16;
        gidx[k][4] = pk[k].z & 0xffff;  gidx[k][5] = ((unsigned)pk[k].z) >> 16;
        gidx[k][6] = pk[k].w & 0xffff;  gidx[k][7] = ((unsigned)pk[k].w) >> 16;
        #pragma unroll
        for (int t = 0; t < 8; t++) {
            const bool dup = (t >= 4 && t <= 6) && (gidx[k][t] == gidx[k][t-3]);
            if (dup) {
                ax[k][t] = ax[k][t-3]; ay[k][t] = ay[k][t-3]; az[k][t] = az[k][t-3];
            } else {
                load_xyz(cp4, cp2, gidx[k][t], ax[k][t], ay[k][t], az[k][t]);
            }
        }
    }

    float v = 0.0f;
    #pragma unroll
    for (int k = 0; k < 2; k++) {
        const float phi = dihedral(&ax[k][0], &ay[k][0], &az[k][0]);
        const float psi = dihedral(&ax[k][4], &ay[k][4], &az[k][4]);

        const int tab = meta[k] & 0xff;
        const float4 tp = __ldg((const float4*)tparams + tab);

        const float u0 = (phi - tp.x) / tp.z;
        const float u1 = (psi - tp.y) / tp.w;
        const float i0f = floorf(u0);
        const float j0f = floorf(u1);
        const float f0 = u0 - i0f;
        const float f1 = u1 - j0f;
        const int i0 = (int)i0f;
        const int j0 = (int)j0f;

        float wp[4], wq[4];
        cr_weights(f0, wp);
        cr_weights(f1, wq);

        const int c0 = wrapG(j0 - 1);
        const int tabbase = tab * NG * NG;

        float4 tv[4];
        #pragma unroll
        for (int i = 0; i < 4; i++) {
            const int ri = wrapG(i0 - 1 + i);
            tv[i] = __ldg(&g_tbl4[tabbase + ri * NG + c0]);
        }

        float e = 0.0f;
        #pragma unroll
        for (int i = 0; i < 4; i++) {
            float acc;
            acc = wq[0] * tv[i].x;
            acc = fmaf(wq[1], tv[i].y, acc);
            acc = fmaf(wq[2], tv[i].z, acc);
            acc = fmaf(wq[3], tv[i].w, acc);
            e = fmaf(wp[i], acc, e);
        }

        v += (((meta[k] >> 8) & 3) == 3) ? e : 0.0f;
    }

    const int lane = tid & 31;
    const int wid  = tid >> 5;
    #pragma unroll
    for (int o = 16; o > 0; o >>= 1)
        v += __shfl_down_sync(0xffffffffu, v, o);
    if (lane == 0) s_warp[wid] = v;
    __syncthreads();
    if (wid == 0) {
        float x = (lane < (TPB / 32)) ? s_warp[lane] : 0.0f;
        #pragma unroll
        for (int o = 4; o > 0; o >>= 1)
            x += __shfl_down_sync(0xffffffffu, x, o);
        if (lane == 0) out[p] = x;
    }
}

extern "C" void kernel_launch(void* const* d_in, const int* in_sizes, int n_in,
                              void* d_out, int out_size) {
    const float* coords        = (const float*)d_in[0];
    const int*   offsets       = (const int*)d_in[1];
    const int*   block_type    = (const int*)d_in[2];
    const int*   inter         = (const int*)d_in[3];
    const int*   down          = (const int*)d_in[4];
    const int*   bt_rama_table = (const int*)d_in[5];
    const int*   bt_upper      = (const int*)d_in[6];
    const int*   bt_is_pro     = (const int*)d_in[7];
    const int*   tor_atoms     = (const int*)d_in[8];
    const float* tables        = (const float*)d_in[9];
    const float* tparams       = (const float*)d_in[10];
    float* out = (float*)d_out;

    const int ntab_elems = NTAB * NG * NG;
    repack_tables_kernel<<<(ntab_elems + 255) / 256, 256>>>(tables);
    prep_kernel<<<NP, TPB>>>(offsets, block_type, inter, down,
                             bt_rama_table, bt_upper, bt_is_pro, tor_atoms);
    score_kernel<<<NP, TPB>>>(coords, tparams, out);
}

// round 13
// speedup vs baseline: 1.0904x; 1.0890x over previous
#include <cuda_runtime.h>
#include <math.h>

#define NP 512
#define NB 512
#define NAT 32
#define NBT 40
#define NC 3
#define NTAB 40
#define NG 36
#define NA (NB*NAT)
#define TPB 256
#define NCELL (NTAB*NG*NG)   // 51840 repacked table cells

// Repacked tables: for each (tab,row,c0), the 4 wrapped column taps as one float4.
__device__ float4 g_tbl4[NCELL];
// Per-item resolved gather indices (8 x u16) and meta (tab | ok<<8 | nb_ok<<9).
__device__ int4 g_pk[NP * NB];
__device__ int  g_meta[NP * NB];

__device__ __forceinline__ int wrapG(int v) {
    int m = v % NG;
    return (m < 0) ? m + NG : m;
}

__device__ __forceinline__ void cr_weights(float f, float w[4]) {
    float f2 = f * f;
    float f3 = f2 * f;
    w[0] = 0.5f * (-f3 + 2.0f * f2 - f);
    w[1] = 0.5f * (3.0f * f3 - 5.0f * f2 + 2.0f);
    w[2] = 0.5f * (-3.0f * f3 + 4.0f * f2 + f);
    w[3] = 0.5f * (f3 - f2);
}

__device__ __forceinline__ float dihedral(
    const float x[4], const float y[4], const float z[4])
{
    float b1x = x[1]-x[0], b1y = y[1]-y[0], b1z = z[1]-z[0];
    float b2x = x[2]-x[1], b2y = y[2]-y[1], b2z = z[2]-z[1];
    float b3x = x[3]-x[2], b3y = y[3]-y[2], b3z = z[3]-z[2];
    float n1x = b1y*b2z - b1z*b2y;
    float n1y = b1z*b2x - b1x*b2z;
    float n1z = b1x*b2y - b1y*b2x;
    float n2x = b2y*b3z - b2z*b3y;
    float n2y = b2z*b3x - b2x*b3z;
    float n2z = b2x*b3y - b2y*b3x;
    float b2n = sqrtf(b2x*b2x + b2y*b2y + b2z*b2z) + 1e-12f;
    float inv = 1.0f / b2n;
    float ux = b2x*inv, uy = b2y*inv, uz = b2z*inv;
    float m1x = n1y*uz - n1z*uy;
    float m1y = n1z*ux - n1x*uz;
    float m1z = n1x*uy - n1y*ux;
    float xx = n1x*n2x + n1y*n2y + n1z*n2z;
    float yy = m1x*n2x + m1y*n2y + m1z*n2z;
    return atan2f(yy, xx);
}

// Branchless xyz load: 1 unconditional LDG.128 + 1 LDG.64 predicated on r>=2.
__device__ __forceinline__ void load_xyz(
    const float4* __restrict__ cp4, const float2* __restrict__ cp2,
    int gidx, float& x, float& y, float& z)
{
    const int base = gidx * 3;
    const int r = base & 3;
    const float4 V = __ldg(cp4 + (base >> 2));
    float2 E = make_float2(0.0f, 0.0f);
    if (r >= 2) E = __ldg(cp2 + ((base + 2) >> 1));
    x = (r == 0) ? V.x : ((r == 1) ? V.y : ((r == 2) ? V.z : V.w));
    y = (r == 0) ? V.y : ((r == 1) ? V.z : ((r == 2) ? V.w : E.x));
    z = (r == 0) ? V.z : ((r == 1) ? V.w : ((r == 2) ? E.x : E.y));
}

// ===== Kernel A (fused): table repack slice + gather-index resolution =====
__global__ __launch_bounds__(TPB, 4) void prep_kernel(
    const int*   __restrict__ offsets,       // (P, B)
    const int*   __restrict__ block_type,    // (P, B)
    const int*   __restrict__ inter,         // (P, B, NC, 2)
    const int*   __restrict__ down,          // (NBT, NC, NAT)
    const int*   __restrict__ bt_rama_table, // (NBT, 2)
    const int*   __restrict__ bt_upper,      // (NBT)
    const int*   __restrict__ bt_is_pro,     // (NBT)
    const int*   __restrict__ tor_atoms,     // (NBT, 8, 3)
    const float* __restrict__ tables)        // (NTAB, G, G)
{
    __shared__ int   s_offs[NB];
    __shared__ int   s_bt[NB];
    __shared__ int4  s_torpack[NBT];
    __shared__ alignas(16) int   s_down[NBT * NC * NAT];
    __shared__ int   s_tabsel[NBT * 2];
    __shared__ int   s_upper[NBT];
    __shared__ int   s_ispro[NBT];

    const int p   = blockIdx.x;
    const int tid = threadIdx.x;

    // ---- repack slice: grid-strided over 51840 cells (<=1 per thread) ----
    {
        const int idx = p * TPB + tid;          // 0 .. 131071
        if (idx < NCELL) {
            const int c0 = idx % NG;
            const float* row = tables + (idx / NG) * NG;
            int c1 = c0 + 1; if (c1 >= NG) c1 -= NG;
            int c2 = c0 + 2; if (c2 >= NG) c2 -= NG;
            int c3 = c0 + 3; if (c3 >= NG) c3 -= NG;
            g_tbl4[idx] = make_float4(row[c0], row[c1], row[c2], row[c3]);
        }
    }

    // ---- stage pose rows ----
    s_offs[tid]       = offsets[p * NB + tid];
    s_offs[tid + TPB] = offsets[p * NB + tid + TPB];
    s_bt[tid]         = block_type[p * NB + tid];
    s_bt[tid + TPB]   = block_type[p * NB + tid + TPB];
    {
        const int4* g4 = (const int4*)down;   // 960 int4
        int4* s4 = (int4*)s_down;
        #pragma unroll
        for (int i = tid; i < 960; i += TPB) s4[i] = g4[i];
    }
    if (tid < NBT) {
        const int* tr = tor_atoms + tid * 24;   // 8 slots x 3
        unsigned int w[4];
        #pragma unroll
        for (int h = 0; h < 4; h++) {
            unsigned int lo, hi;
            {
                const int s = 2 * h;
                const int ai = tr[s*3+0], ci = tr[s*3+1], nb = tr[s*3+2];
                lo = (unsigned int)(ai + 1) | ((unsigned int)(ci + 1) << 6)
                   | ((unsigned int)nb << 8);
            }
            {
                const int s = 2 * h + 1;
                const int ai = tr[s*3+0], ci = tr[s*3+1], nb = tr[s*3+2];
                hi = (unsigned int)(ai + 1) | ((unsigned int)(ci + 1) << 6)
                   | ((unsigned int)nb << 8);
            }
            w[h] = lo | (hi << 16);
        }
        s_torpack[tid] = make_int4((int)w[0], (int)w[1], (int)w[2], (int)w[3]);
    }
    if (tid < NBT * 2) s_tabsel[tid] = bt_rama_table[tid];
    if (tid < NBT)     { s_upper[tid] = bt_upper[tid]; s_ispro[tid] = bt_is_pro[tid]; }

    int iv[2][6];
    #pragma unroll
    for (int k = 0; k < 2; k++) {
        const int pb = p * NB + tid + k * TPB;
        const int2* ip2 = (const int2*)(inter + (size_t)pb * 6);
        const int2 a = __ldg(ip2 + 0), bb = __ldg(ip2 + 1), c = __ldg(ip2 + 2);
        iv[k][0] = a.x;  iv[k][1] = a.y;
        iv[k][2] = bb.x; iv[k][3] = bb.y;
        iv[k][4] = c.x;  iv[k][5] = c.y;
    }

    __syncthreads();

    #pragma unroll
    for (int k = 0; k < 2; k++) {
        const int b    = tid + k * TPB;
        const int pb   = p * NB + b;
        const int bt   = s_bt[b];
        const int offb = s_offs[b];
        const int4 tp4 = s_torpack[bt];
        bool okk = true;
        int g[8];
        #pragma unroll
        for (int t = 0; t < 8; t++) {
            const unsigned int word = (unsigned int)((t >> 1) == 0 ? tp4.x :
                                      (t >> 1) == 1 ? tp4.y :
                                      (t >> 1) == 2 ? tp4.z : tp4.w);
            const unsigned int field = (t & 1) ? (word >> 16) : (word & 0xffffu);
            const int ai     = (int)(field & 63u) - 1;
            const int ci     = (int)((field >> 6) & 3u) - 1;
            const int nbonds = (int)((field >> 8) & 31u);
            int gg;
            bool aok;
            if (ai >= 0) {
                gg = offb + ai;
                aok = true;
            } else {
                const int sc = max(ci, 0);
                const int ob = (sc == 0) ? iv[k][0] : ((sc == 1) ? iv[k][2] : iv[k][4]);
                const int oc = (sc == 0) ? iv[k][1] : ((sc == 1) ? iv[k][3] : iv[k][5]);
                aok = (ci >= 0) && (ob >= 0);
                const int obc = min(max(ob, 0), NB - 1);
                const int occ = min(max(oc, 0), NC - 1);
                const int obt = s_bt[obc];
                const int da  = s_down[(obt * NC + occ) * NAT + nbonds];
                gg = s_offs[obc] + da;
            }
            okk = okk && aok;
            g[t] = min(max(gg, 0), NA - 1);
        }

        const int uc    = min(max(s_upper[bt], 0), NC - 1);
        const int nbblk = (uc == 0) ? iv[k][0] : ((uc == 1) ? iv[k][2] : iv[k][4]);
        const bool nb_ok = (nbblk >= 0);
        const int nbt = s_bt[min(max(nbblk, 0), NB - 1)];
        const int tab = s_tabsel[bt * 2 + s_ispro[nbt]];

        int4 pk;
        pk.x = g[0] | (g[1] << 16);
        pk.y = g[2] | (g[3] << 16);
        pk.z = g[4] | (g[5] << 16);
        pk.w = g[6] | (g[7] << 16);
        g_pk[pb]   = pk;
        g_meta[pb] = tab | (okk ? 0x100 : 0) | (nb_ok ? 0x200 : 0);
    }
}

// ===== Kernel B: gather coords, dihedrals, table energy, reduce =====
__global__ __launch_bounds__(TPB, 4) void score_kernel(
    const float* __restrict__ coords,        // (P, NA, 3)
    const float* __restrict__ tparams,       // (NTAB, 2, 2)
    float*       __restrict__ out)           // (P,)
{
    __shared__ float s_warp[TPB / 32];

    const int p   = blockIdx.x;
    const int tid = threadIdx.x;

    const float4* cp4 = (const float4*)(coords + (size_t)p * NA * 3);
    const float2* cp2 = (const float2*)(coords + (size_t)p * NA * 3);

    int4 pk[2];
    int  meta[2];
    #pragma unroll
    for (int k = 0; k < 2; k++) {
        const int pb = p * NB + tid + k * TPB;
        pk[k]   = __ldg(&g_pk[pb]);
        meta[k] = __ldg(&g_meta[pb]);
    }

    int gidx[2][8];
    float ax[2][8], ay[2][8], az[2][8];
    #pragma unroll
    for (int k = 0; k < 2; k++) {
        gidx[k][0] = pk[k].x & 0xffff;  gidx[k][1] = ((unsigned)pk[k].x) >> 16;
        gidx[k][2] = pk[k].y & 0xffff;  gidx[k][3] = ((unsigned)pk[k].y) >> 16;
        gidx[k][4] = pk[k].z & 0xffff;  gidx[k][5] = ((unsigned)pk[k].z) >> 16;
        gidx[k][6] = pk[k].w & 0xffff;  gidx[k][7] = ((unsigned)pk[k].w) >> 16;
        #pragma unroll
        for (int t = 0; t < 8; t++) {
            const bool dup = (t >= 4 && t <= 6) && (gidx[k][t] == gidx[k][t-3]);
            if (dup) {
                ax[k][t] = ax[k][t-3]; ay[k][t] = ay[k][t-3]; az[k][t] = az[k][t-3];
            } else {
                load_xyz(cp4, cp2, gidx[k][t], ax[k][t], ay[k][t], az[k][t]);
            }
        }
    }

    float v = 0.0f;
    #pragma unroll
    for (int k = 0; k < 2; k++) {
        const float phi = dihedral(&ax[k][0], &ay[k][0], &az[k][0]);
        const float psi = dihedral(&ax[k][4], &ay[k][4], &az[k][4]);

        const int tab = meta[k] & 0xff;
        const float4 tp = __ldg((const float4*)tparams + tab);

        const float u0 = (phi - tp.x) / tp.z;
        const float u1 = (psi - tp.y) / tp.w;
        const float i0f = floorf(u0);
        const float j0f = floorf(u1);
        const float f0 = u0 - i0f;
        const float f1 = u1 - j0f;
        const int i0 = (int)i0f;
        const int j0 = (int)j0f;

        float wp[4], wq[4];
        cr_weights(f0, wp);
        cr_weights(f1, wq);

        const int c0 = wrapG(j0 - 1);
        const int tabbase = tab * NG * NG;

        float4 tv[4];
        #pragma unroll
        for (int i = 0; i < 4; i++) {
            const int ri = wrapG(i0 - 1 + i);
            tv[i] = __ldg(&g_tbl4[tabbase + ri * NG + c0]);
        }

        float e = 0.0f;
        #pragma unroll
        for (int i = 0; i < 4; i++) {
            float acc;
            acc = wq[0] * tv[i].x;
            acc = fmaf(wq[1], tv[i].y, acc);
            acc = fmaf(wq[2], tv[i].z, acc);
            acc = fmaf(wq[3], tv[i].w, acc);
            e = fmaf(wp[i], acc, e);
        }

        v += (((meta[k] >> 8) & 3) == 3) ? e : 0.0f;
    }

    const int lane = tid & 31;
    const int wid  = tid >> 5;
    #pragma unroll
    for (int o = 16; o > 0; o >>= 1)
        v += __shfl_down_sync(0xffffffffu, v, o);
    if (lane == 0) s_warp[wid] = v;
    __syncthreads();
    if (wid == 0) {
        float x = (lane < (TPB / 32)) ? s_warp[lane] : 0.0f;
        #pragma unroll
        for (int o = 4; o > 0; o >>= 1)
            x += __shfl_down_sync(0xffffffffu, x, o);
        if (lane == 0) out[p] = x;
    }
}

extern "C" void kernel_launch(void* const* d_in, const int* in_sizes, int n_in,
                              void* d_out, int out_size) {
    const float* coords        = (const float*)d_in[0];
    const int*   offsets       = (const int*)d_in[1];
    const int*   block_type    = (const int*)d_in[2];
    const int*   inter         = (const int*)d_in[3];
    const int*   down          = (const int*)d_in[4];
    const int*   bt_rama_table = (const int*)d_in[5];
    const int*   bt_upper      = (const int*)d_in[6];
    const int*   bt_is_pro     = (const int*)d_in[7];
    const int*   tor_atoms     = (const int*)d_in[8];
    const float* tables        = (const float*)d_in[9];
    const float* tparams       = (const float*)d_in[10];
    float* out = (float*)d_out;

    prep_kernel<<<NP, TPB>>>(offsets, block_type, inter, down,
                             bt_rama_table, bt_upper, bt_is_pro, tor_atoms,
                             tables);
    score_kernel<<<NP, TPB>>>(coords, tparams, out);
}